// round 16
// baseline (speedup 1.0000x reference)
#include <cuda_runtime.h>
#include <cuda_fp16.h>
#include <cstdint>
#include <cstddef>

// Problem constants
#define BATCH 8
#define NSEQ  1032          // 32*32 + 8
#define NSEQP 1088          // padded to 17*64
#define CDIM  768
#define HEADS 12
#define HD    64
#define MROWS (BATCH*NSEQ)  // 8256
#define KVW   1536          // k+v columns
#define KH    768           // fp16 K-extent
#define NPANEL (BATCH*HEADS) // 96

// Device scratch (static globals — zero-initialized, no runtime allocation).
__device__ __half g_xh  [(size_t)MROWS * KH];      // x fp16
__device__ __half g_atth[(size_t)MROWS * KH];      // attn out fp16 (attn epilogue)
__device__ __half g_wkvh[(size_t)KVW   * KH];      // qkv_w rows 768..2303 fp16
__device__ __half g_wprjh[(size_t)CDIM * KH];      // proj_w fp16
__device__ __half g_vh[(size_t)MROWS * CDIM];      // V fp16 [row][hd] (gemm_kv epilogue)
__device__ __half g_kc[(size_t)NPANEL * NSEQP * 64];   // per (b,h): [j][d] K fp16
__device__ __half g_vt[(size_t)NPANEL * 64 * NSEQP];   // per (b,h): [d][j] V^T fp16

// ---------------------------------------------------------------------------
// Helpers (portable PTX: ldmatrix / mma.sync / cp.async)
// ---------------------------------------------------------------------------
__device__ __forceinline__ uint32_t smem_u32(const void* p) {
    uint32_t a;
    asm("{ .reg .u64 t; cvta.to.shared.u64 t, %1; cvt.u32.u64 %0, t; }" : "=r"(a) : "l"(p));
    return a;
}
#define SMEM_SWIZZLE_128B(x) ((x) ^ (((x) >> 3) & 0x70))

#define CP_ASYNC16(sa, ga) \
    asm volatile("cp.async.cg.shared.global [%0], [%1], 16;" :: "r"(sa), "l"(ga) : "memory")
#define CP_COMMIT() asm volatile("cp.async.commit_group;" ::: "memory")
#define CP_WAIT1()  asm volatile("cp.async.wait_group 1;" ::: "memory")
#define CP_WAIT0()  asm volatile("cp.async.wait_group 0;" ::: "memory")

__device__ __forceinline__ void ldsm_x4(uint32_t* r, uint32_t addr) {
    asm volatile("ldmatrix.sync.aligned.m8n8.x4.shared.b16 {%0,%1,%2,%3}, [%4];"
                 : "=r"(r[0]), "=r"(r[1]), "=r"(r[2]), "=r"(r[3]) : "r"(addr));
}

__device__ __forceinline__ void mma_16816(float* c, const uint32_t* a,
                                          uint32_t b0, uint32_t b1) {
    asm volatile("mma.sync.aligned.m16n8k16.row.col.f32.f16.f16.f32 "
                 "{%0,%1,%2,%3}, {%4,%5,%6,%7}, {%8,%9}, {%0,%1,%2,%3};"
                 : "+f"(c[0]), "+f"(c[1]), "+f"(c[2]), "+f"(c[3])
                 : "r"(a[0]), "r"(a[1]), "r"(a[2]), "r"(a[3]), "r"(b0), "r"(b1));
}

// ---------------------------------------------------------------------------
// Combined fp16 conversion: x -> g_xh, qkv_w rows 768.. -> g_wkvh,
// proj_w -> g_wprjh. All sources are contiguous row-major K=768, so this is
// one linear copy-convert over float4 units.
// ---------------------------------------------------------------------------
#define CV_NX ((size_t)MROWS * 192)
#define CV_NW ((size_t)KVW * 192)
#define CV_NP ((size_t)CDIM * 192)

__global__ __launch_bounds__(256) void conv_all_kernel(
    const float* __restrict__ x, const float* __restrict__ qkv_w,
    const float* __restrict__ proj_w)
{
    size_t idx = (size_t)blockIdx.x * blockDim.x + threadIdx.x;
    const float* src; __half* dst;
    if (idx < CV_NX)                 { src = x; dst = g_xh; }
    else if (idx < CV_NX + CV_NW)    { idx -= CV_NX; src = qkv_w + (size_t)CDIM * CDIM; dst = g_wkvh; }
    else if (idx < CV_NX + CV_NW + CV_NP) { idx -= CV_NX + CV_NW; src = proj_w; dst = g_wprjh; }
    else return;

    float4 v = ((const float4*)src)[idx];
    __half2 a, b;
    a.x = __float2half_rn(v.x); a.y = __float2half_rn(v.y);
    b.x = __float2half_rn(v.z); b.y = __float2half_rn(v.w);
    ((__half2*)dst)[idx * 2]     = a;
    ((__half2*)dst)[idx * 2 + 1] = b;
}

// ---------------------------------------------------------------------------
// V transpose: g_vh fp16 [row][hd] -> g_vt fp16 [bh][d][j]
// ---------------------------------------------------------------------------
__global__ __launch_bounds__(256) void conv_vt_kernel()
{
    __shared__ float vt[64][65];
    const int tid = threadIdx.x;
    const int bh = blockIdx.y, b = bh / HEADS, h = bh % HEADS;
    const int j0 = blockIdx.x * 64;

#pragma unroll
    for (int it = 0; it < 16; it++) {
        int idx = tid + 256 * it;
        int j = idx >> 6, d = idx & 63;
        int gj = j0 + j;
        float vvv = 0.0f;
        if (gj < NSEQ)
            vvv = __half2float(g_vh[(size_t)(b * NSEQ + gj) * CDIM + h * HD + d]);
        vt[j][d] = vvv;
    }
    __syncthreads();
#pragma unroll
    for (int it = 0; it < 16; it++) {
        int idx = tid + 256 * it;
        int d = idx >> 6, j = idx & 63;
        int gj = j0 + j;
        if (gj < NSEQ)
            g_vt[((size_t)bh * 64 + d) * NSEQP + gj] = __float2half_rn(vt[j][d]);
    }
}

// ---------------------------------------------------------------------------
// HMMA fp16 GEMM over K=768. 3-stage cp.async pipeline, ONE barrier per stage.
// which==0 (K,V proj): epilogue writes g_kc (K cols, fp16) + g_vh (V cols).
// which==1 (out proj): epilogue writes fp32 out + bias.
// ---------------------------------------------------------------------------
#define GEMM_SMEM 98304   // 3 stages x (A 16KB + B 16KB)

__global__ __launch_bounds__(256, 2) void gemm_mma_kernel(
    int which, const float* __restrict__ bias, float* __restrict__ outp)
{
    extern __shared__ __align__(128) char smem[];
    const uint32_t sb = smem_u32(smem);

    const __half* __restrict__ A  = which ? g_atth : g_xh;
    const __half* __restrict__ Bw = which ? g_wprjh : g_wkvh;

    const int tid  = threadIdx.x;
    const int lane = tid & 31;
    const int w    = tid >> 5;
    const int wm   = w >> 2;
    const int wn   = w & 3;
    const int n0   = blockIdx.x * 128;
    const int m0   = blockIdx.y * 128;

    float acc[4][4][4];
#pragma unroll
    for (int mi = 0; mi < 4; mi++)
#pragma unroll
        for (int ni = 0; ni < 4; ni++)
#pragma unroll
            for (int c = 0; c < 4; c++) acc[mi][ni][c] = 0.0f;

    const int srow = tid >> 3;
    const int q    = tid & 7;

    auto issue_stage = [&](int ch, int buf) {
        const uint32_t sa_base = sb + (uint32_t)buf * 32768u;
        const uint32_t sb_base = sa_base + 16384u;
#pragma unroll
        for (int u = 0; u < 4; u++) {
            const int row = srow + 32 * u;
            int am = m0 + row; if (am > MROWS - 1) am = MROWS - 1;
            const uint32_t so = SMEM_SWIZZLE_128B((uint32_t)(row * 128 + q * 16));
            CP_ASYNC16(sa_base + so, A  + (size_t)am * KH + ch * 64 + q * 8);
            CP_ASYNC16(sb_base + so, Bw + (size_t)(n0 + row) * KH + ch * 64 + q * 8);
        }
        CP_COMMIT();
    };

    const int NSTAGE = KH / 64;      // 12
    issue_stage(0, 0);
    issue_stage(1, 1);

    for (int ch = 0; ch < NSTAGE; ch++) {
        if (ch + 1 < NSTAGE) CP_WAIT1(); else CP_WAIT0();
        __syncthreads();   // stage ch resident for all; all warps done with ch-1
        if (ch + 2 < NSTAGE) issue_stage(ch + 2, (ch + 2) % 3);

        const uint32_t abase = sb + (uint32_t)(ch % 3) * 32768u;
        const uint32_t bbase = abase + 16384u;
        const int rsel = lane & 15;
        const int chi  = lane >> 4;

#pragma unroll
        for (int kk = 0; kk < 4; kk++) {
            const int c8 = kk * 2 + chi;
            uint32_t af[4][4], bfr[2][4];
#pragma unroll
            for (int mi = 0; mi < 4; mi++) {
                const int row = wm * 64 + mi * 16 + rsel;
                ldsm_x4(af[mi], abase + SMEM_SWIZZLE_128B((uint32_t)(row * 128 + c8 * 16)));
            }
#pragma unroll
            for (int g = 0; g < 2; g++) {
                const int row = wn * 32 + g * 16 + rsel;
                ldsm_x4(bfr[g], bbase + SMEM_SWIZZLE_128B((uint32_t)(row * 128 + c8 * 16)));
            }
#pragma unroll
            for (int mi = 0; mi < 4; mi++)
#pragma unroll
                for (int ni = 0; ni < 4; ni++) {
                    const int g = ni >> 1, o = ni & 1;
                    mma_16816(acc[mi][ni], af[mi], bfr[g][o], bfr[g][o + 2]);
                }
        }
        // no trailing barrier: next-iter top barrier orders buffer reuse
    }

    // Epilogue
#pragma unroll
    for (int mi = 0; mi < 4; mi++) {
        const int r0 = m0 + wm * 64 + mi * 16 + (lane >> 2);
        const int r1 = r0 + 8;
#pragma unroll
        for (int ni = 0; ni < 4; ni++) {
            const int col = n0 + wn * 32 + ni * 8 + (lane & 3) * 2;
            const float b0v = bias[col], b1v = bias[col + 1];
            if (which) {
                if (r0 < MROWS) {
                    float2 v = make_float2(acc[mi][ni][0] + b0v, acc[mi][ni][1] + b1v);
                    *(float2*)(outp + (size_t)r0 * CDIM + col) = v;
                }
                if (r1 < MROWS) {
                    float2 v = make_float2(acc[mi][ni][2] + b0v, acc[mi][ni][3] + b1v);
                    *(float2*)(outp + (size_t)r1 * CDIM + col) = v;
                }
            } else {
                // K,V projection: K cols -> g_kc fp16; V cols -> g_vh fp16.
                // n0 is 128-aligned so (col < 768) is uniform per CTA.
#pragma unroll
                for (int half2sel = 0; half2sel < 2; half2sel++) {
                    const int r = half2sel ? r1 : r0;
                    if (r >= MROWS) continue;
                    const float v0 = acc[mi][ni][half2sel * 2]     + b0v;
                    const float v1 = acc[mi][ni][half2sel * 2 + 1] + b1v;
                    __half2 hv;
                    hv.x = __float2half_rn(v0); hv.y = __float2half_rn(v1);
                    if (col < CDIM) {
                        const int bb = r / NSEQ, j = r - bb * NSEQ;
                        const int hh = col >> 6, d = col & 63;
                        *(__half2*)(g_kc + ((size_t)(bb * HEADS + hh) * NSEQP + j) * 64 + d) = hv;
                    } else {
                        *(__half2*)(g_vh + (size_t)r * CDIM + (col - CDIM)) = hv;
                    }
                }
            }
        }
    }
}

// ---------------------------------------------------------------------------
// Tensor-core flash attention, fp16, 2-stage j-tile pipeline (ONE barrier/tile).
// Smem: Ki 16KB | 2 stages x (KJ 8KB + VT 8KB) | P 16KB | ftab -> 64.3KB.
// 2 CTAs/SM preserved (128.6KB <= 228KB), regs capped by (256,2).
// ---------------------------------------------------------------------------
#define AK_KI    0
#define AK_STG(t) (16384 + (t) * 16384)   // KJ +0, VT +8192
#define AK_P     49152
#define AK_FTAB  65536
#define AK_SMEM  (65536 + 256)

__global__ __launch_bounds__(256, 2) void attn_mma_kernel()
{
    extern __shared__ __align__(128) char sm[];
    const uint32_t sb = smem_u32(sm);
    float* ftab = (float*)(sm + AK_FTAB);

    const int tid = threadIdx.x, lane = tid & 31, w = tid >> 5;
    const int bh = blockIdx.y, b = bh / HEADS, h = bh % HEADS;
    const int i0 = blockIdx.x * 128;

    if (tid < 63) { float xx = (float)tid - 31.0f; ftab[tid] = __expf(-xx * xx * 0.02f); }

    const int srow = tid >> 3, q = tid & 7;

    auto issue_jtile = [&](int jt, int t) {
        const uint32_t stg = sb + AK_STG(t);
#pragma unroll
        for (int u = 0; u < 2; u++) {
            int row = srow + 32 * u;
            const __half* sk = g_kc + ((size_t)bh * NSEQP + jt + row) * 64 + q * 8;
            const __half* sv = g_vt + ((size_t)bh * 64 + row) * NSEQP + jt + q * 8;
            uint32_t so = SMEM_SWIZZLE_128B((uint32_t)(row * 128 + q * 16));
            CP_ASYNC16(stg +         so, sk);
            CP_ASYNC16(stg + 8192u + so, sv);
        }
        CP_COMMIT();
    };

    // Prologue: Ki + first j-tile
    {
#pragma unroll
        for (int u = 0; u < 4; u++) {
            int row = srow + 32 * u;
            int gi = i0 + row; if (gi > NSEQ - 1) gi = NSEQ - 1;
            const __half* src = g_kc + ((size_t)bh * NSEQP + gi) * 64 + q * 8;
            uint32_t so = SMEM_SWIZZLE_128B((uint32_t)(row * 128 + q * 16));
            CP_ASYNC16(sb + AK_KI + so, src);
        }
        CP_COMMIT();
        issue_jtile(0, 0);
    }

    const int rsel = lane & 15, chi = lane >> 4;
    const int rA = w * 16 + (lane >> 2);
    const int iA = i0 + rA, iB = iA + 8;
    const bool okA = (iA >= 8) && (iA < NSEQ);
    const bool okB = (iB >= 8) && (iB < NSEQ);
    const int qiA1 = (iA - 8) >> 5, qiA2 = (iA - 8) & 31;
    const int qiB1 = (iB - 8) >> 5, qiB2 = (iB - 8) & 31;

    float mA = -1e30f, mB = -1e30f, lA = 0.0f, lB = 0.0f;
    float O[8][4];
#pragma unroll
    for (int ni = 0; ni < 8; ni++)
#pragma unroll
        for (int c = 0; c < 4; c++) O[ni][c] = 0.0f;

    const float scale = 0.125f;

    for (int jt = 0; jt < NSEQP; jt += 64) {
        const int t = (jt >> 6) & 1;
        CP_WAIT0();        // tile jt (+Ki first iter) resident
        __syncthreads();   // all warps past PV of jt-64 -> stage t^1 free
        if (jt + 64 < NSEQP) issue_jtile(jt + 64, t ^ 1);   // overlaps full tile body

        const uint32_t kjb = sb + AK_STG(t);
        const uint32_t vtb = kjb + 8192u;

        // ---- S = Ki.Kj^T (single fp16 pass) ----
        float s[8][4];
#pragma unroll
        for (int ni = 0; ni < 8; ni++)
#pragma unroll
            for (int c = 0; c < 4; c++) s[ni][c] = 0.0f;

#pragma unroll
        for (int kk = 0; kk < 4; kk++) {
            const int c8 = kk * 2 + chi;
            uint32_t af[4], bfr[4][4];
            ldsm_x4(af, sb + AK_KI +
                    SMEM_SWIZZLE_128B((uint32_t)((w * 16 + rsel) * 128 + c8 * 16)));
#pragma unroll
            for (int g = 0; g < 4; g++)
                ldsm_x4(bfr[g], kjb +
                        SMEM_SWIZZLE_128B((uint32_t)((g * 16 + rsel) * 128 + c8 * 16)));
#pragma unroll
            for (int ni = 0; ni < 8; ni++)
                mma_16816(s[ni], af, bfr[ni >> 1][ni & 1], bfr[ni >> 1][(ni & 1) + 2]);
        }

        // ---- scale + gaussian bias + tail mask ----
#pragma unroll
        for (int ni = 0; ni < 8; ni++) {
            const int jbase = jt + ni * 8 + ((lane & 3) << 1);
#pragma unroll
            for (int c = 0; c < 4; c++) {
                const int j = jbase + (c & 1);
                float val = s[ni][c] * scale;
                const bool ok = (c < 2) ? okA : okB;
                const int q1 = (c < 2) ? qiA1 : qiB1;
                const int q2 = (c < 2) ? qiA2 : qiB2;
                if (j < NSEQ) {
                    if (ok && j >= 8)
                        val += ftab[q1 - ((j - 8) >> 5) + 31] * ftab[q2 - ((j - 8) & 31) + 31];
                } else val = -1e30f;
                s[ni][c] = val;
            }
        }

        // ---- online softmax ----
        float tA = -1e30f, tB = -1e30f;
#pragma unroll
        for (int ni = 0; ni < 8; ni++) {
            tA = fmaxf(tA, fmaxf(s[ni][0], s[ni][1]));
            tB = fmaxf(tB, fmaxf(s[ni][2], s[ni][3]));
        }
        tA = fmaxf(tA, __shfl_xor_sync(0xffffffffu, tA, 1));
        tA = fmaxf(tA, __shfl_xor_sync(0xffffffffu, tA, 2));
        tB = fmaxf(tB, __shfl_xor_sync(0xffffffffu, tB, 1));
        tB = fmaxf(tB, __shfl_xor_sync(0xffffffffu, tB, 2));
        const float mnA = fmaxf(mA, tA), mnB = fmaxf(mB, tB);
        const float cA = __expf(mA - mnA), cB = __expf(mB - mnB);
        float rsA = 0.0f, rsB = 0.0f;
#pragma unroll
        for (int ni = 0; ni < 8; ni++) {
            s[ni][0] = __expf(s[ni][0] - mnA); rsA += s[ni][0];
            s[ni][1] = __expf(s[ni][1] - mnA); rsA += s[ni][1];
            s[ni][2] = __expf(s[ni][2] - mnB); rsB += s[ni][2];
            s[ni][3] = __expf(s[ni][3] - mnB); rsB += s[ni][3];
        }
        rsA += __shfl_xor_sync(0xffffffffu, rsA, 1);
        rsA += __shfl_xor_sync(0xffffffffu, rsA, 2);
        rsB += __shfl_xor_sync(0xffffffffu, rsB, 1);
        rsB += __shfl_xor_sync(0xffffffffu, rsB, 2);
        lA = lA * cA + rsA; lB = lB * cB + rsB;
        mA = mnA; mB = mnB;

        // ---- P -> smem (fp16, warp-private rows) + O rescale ----
        const uint32_t rowoffA = (uint32_t)((w * 16 + (lane >> 2)) * 128 + (lane & 3) * 4);
        const uint32_t rowoffB = rowoffA + 8 * 128;
#pragma unroll
        for (int ni = 0; ni < 8; ni++) {
            O[ni][0] *= cA; O[ni][1] *= cA; O[ni][2] *= cB; O[ni][3] *= cB;

            __half2 pv;
            pv.x = __float2half_rn(s[ni][0]); pv.y = __float2half_rn(s[ni][1]);
            *(__half2*)(sm + AK_P + SMEM_SWIZZLE_128B(rowoffA + ni * 16)) = pv;

            __half2 pv2;
            pv2.x = __float2half_rn(s[ni][2]); pv2.y = __float2half_rn(s[ni][3]);
            *(__half2*)(sm + AK_P + SMEM_SWIZZLE_128B(rowoffB + ni * 16)) = pv2;
        }
        __syncwarp();

        // ---- O += P.V (single fp16 pass) ----
#pragma unroll
        for (int kk = 0; kk < 4; kk++) {
            const int c8 = kk * 2 + chi;
            uint32_t af[4], bfr[4][4];
            ldsm_x4(af, sb + AK_P +
                    SMEM_SWIZZLE_128B((uint32_t)((w * 16 + rsel) * 128 + c8 * 16)));
#pragma unroll
            for (int g = 0; g < 4; g++)
                ldsm_x4(bfr[g], vtb +
                        SMEM_SWIZZLE_128B((uint32_t)((g * 16 + rsel) * 128 + c8 * 16)));
#pragma unroll
            for (int ni = 0; ni < 8; ni++)
                mma_16816(O[ni], af, bfr[ni >> 1][ni & 1], bfr[ni >> 1][(ni & 1) + 2]);
        }
    }

    // ---- epilogue: normalize, write g_atth fp16 directly ----
    const float invA = 1.0f / lA, invB = 1.0f / lB;
#pragma unroll
    for (int ni = 0; ni < 8; ni++) {
        const int d = ni * 8 + ((lane & 3) << 1);
        if (iA < NSEQ) {
            __half2 v;
            v.x = __float2half_rn(O[ni][0] * invA);
            v.y = __float2half_rn(O[ni][1] * invA);
            *(__half2*)(g_atth + (size_t)(b * NSEQ + iA) * KH + h * HD + d) = v;
        }
        if (iB < NSEQ) {
            __half2 v;
            v.x = __float2half_rn(O[ni][2] * invB);
            v.y = __float2half_rn(O[ni][3] * invB);
            *(__half2*)(g_atth + (size_t)(b * NSEQ + iB) * KH + h * HD + d) = v;
        }
    }
}

// ---------------------------------------------------------------------------
extern "C" void kernel_launch(void* const* d_in, const int* in_sizes, int n_in,
                              void* d_out, int out_size)
{
    const float* x = nullptr;
    const float* qkv_w = nullptr;
    const float* qkv_b = nullptr;
    const float* proj_w = nullptr;
    const float* proj_b = nullptr;
    for (int i = 0; i < n_in; i++) {
        switch (in_sizes[i]) {
            case 6340608: x      = (const float*)d_in[i]; break;
            case 1769472: qkv_w  = (const float*)d_in[i]; break;
            case 2304:    qkv_b  = (const float*)d_in[i]; break;
            case 589824:  proj_w = (const float*)d_in[i]; break;
            case 768:     proj_b = (const float*)d_in[i]; break;
        }
    }
    float* out = (float*)d_out;

    cudaFuncSetAttribute(gemm_mma_kernel, cudaFuncAttributeMaxDynamicSharedMemorySize, GEMM_SMEM);
    cudaFuncSetAttribute(attn_mma_kernel, cudaFuncAttributeMaxDynamicSharedMemorySize, AK_SMEM);

    // 0) combined conversion: x, W_kv, W_proj -> fp16 (one launch)
    {
        size_t total = CV_NX + CV_NW + CV_NP;
        conv_all_kernel<<<(unsigned)((total + 255) / 256), 256>>>(x, qkv_w, proj_w);
    }
    // 1) K,V projection via fp16 HMMA -> g_kc (K, fp16 direct) + g_vh (V fp16)
    {
        dim3 grid(KVW / 128, (MROWS + 127) / 128);   // 12 x 65
        gemm_mma_kernel<<<grid, 256, GEMM_SMEM>>>(0, qkv_b + CDIM, nullptr);
    }
    // 2) V transpose -> g_vt
    {
        dim3 grid(17, NPANEL);                       // 17 x 96
        conv_vt_kernel<<<grid, 256>>>();
    }
    // 3) tensor-core flash attention -> g_atth (fp16, direct)
    {
        dim3 grid((NSEQ + 127) / 128, NPANEL);       // 9 x 96
        attn_mma_kernel<<<grid, 256, AK_SMEM>>>();
    }
    // 4) output projection via fp16 HMMA -> d_out
    {
        dim3 grid(CDIM / 128, (MROWS + 127) / 128);  // 6 x 65
        gemm_mma_kernel<<<grid, 256, GEMM_SMEM>>>(1, proj_b, out);
    }
}

// round 17
// speedup vs baseline: 1.0929x; 1.0929x over previous
#include <cuda_runtime.h>
#include <cuda_fp16.h>
#include <cstdint>
#include <cstddef>

// Problem constants
#define BATCH 8
#define NSEQ  1032          // 32*32 + 8
#define NSEQP 1088          // padded to 17*64
#define CDIM  768
#define HEADS 12
#define HD    64
#define MROWS (BATCH*NSEQ)  // 8256
#define KVW   1536          // k+v columns
#define KH    768           // fp16 K-extent
#define NPANEL (BATCH*HEADS) // 96

// Device scratch (static globals — zero-initialized, no runtime allocation).
__device__ __half g_xh  [(size_t)MROWS * KH];      // x fp16
__device__ __half g_atth[(size_t)MROWS * KH];      // attn out fp16 (attn epilogue)
__device__ __half g_wkvh[(size_t)KVW   * KH];      // qkv_w rows 768..2303 fp16
__device__ __half g_wprjh[(size_t)CDIM * KH];      // proj_w fp16
__device__ __half g_vh[(size_t)MROWS * CDIM];      // V fp16 [row][hd] (gemm_kv epilogue)
__device__ __half g_kc[(size_t)NPANEL * NSEQP * 64];   // per (b,h): [j][d] K fp16
__device__ __half g_vt[(size_t)NPANEL * 64 * NSEQP];   // per (b,h): [d][j] V^T fp16

// ---------------------------------------------------------------------------
// Helpers (portable PTX: ldmatrix / mma.sync / cp.async)
// ---------------------------------------------------------------------------
__device__ __forceinline__ uint32_t smem_u32(const void* p) {
    uint32_t a;
    asm("{ .reg .u64 t; cvta.to.shared.u64 t, %1; cvt.u32.u64 %0, t; }" : "=r"(a) : "l"(p));
    return a;
}
#define SMEM_SWIZZLE_128B(x) ((x) ^ (((x) >> 3) & 0x70))

#define CP_ASYNC16(sa, ga) \
    asm volatile("cp.async.cg.shared.global [%0], [%1], 16;" :: "r"(sa), "l"(ga) : "memory")
#define CP_COMMIT() asm volatile("cp.async.commit_group;" ::: "memory")
#define CP_WAIT1()  asm volatile("cp.async.wait_group 1;" ::: "memory")
#define CP_WAIT0()  asm volatile("cp.async.wait_group 0;" ::: "memory")

__device__ __forceinline__ void ldsm_x4(uint32_t* r, uint32_t addr) {
    asm volatile("ldmatrix.sync.aligned.m8n8.x4.shared.b16 {%0,%1,%2,%3}, [%4];"
                 : "=r"(r[0]), "=r"(r[1]), "=r"(r[2]), "=r"(r[3]) : "r"(addr));
}

__device__ __forceinline__ void mma_16816(float* c, const uint32_t* a,
                                          uint32_t b0, uint32_t b1) {
    asm volatile("mma.sync.aligned.m16n8k16.row.col.f32.f16.f16.f32 "
                 "{%0,%1,%2,%3}, {%4,%5,%6,%7}, {%8,%9}, {%0,%1,%2,%3};"
                 : "+f"(c[0]), "+f"(c[1]), "+f"(c[2]), "+f"(c[3])
                 : "r"(a[0]), "r"(a[1]), "r"(a[2]), "r"(a[3]), "r"(b0), "r"(b1));
}

// ---------------------------------------------------------------------------
// Combined fp16 conversion: x -> g_xh, qkv_w rows 768.. -> g_wkvh,
// proj_w -> g_wprjh. One linear copy-convert over float4 units. (verified R16)
// ---------------------------------------------------------------------------
#define CV_NX ((size_t)MROWS * 192)
#define CV_NW ((size_t)KVW * 192)
#define CV_NP ((size_t)CDIM * 192)

__global__ __launch_bounds__(256) void conv_all_kernel(
    const float* __restrict__ x, const float* __restrict__ qkv_w,
    const float* __restrict__ proj_w)
{
    size_t idx = (size_t)blockIdx.x * blockDim.x + threadIdx.x;
    const float* src; __half* dst;
    if (idx < CV_NX)                 { src = x; dst = g_xh; }
    else if (idx < CV_NX + CV_NW)    { idx -= CV_NX; src = qkv_w + (size_t)CDIM * CDIM; dst = g_wkvh; }
    else if (idx < CV_NX + CV_NW + CV_NP) { idx -= CV_NX + CV_NW; src = proj_w; dst = g_wprjh; }
    else return;

    float4 v = ((const float4*)src)[idx];
    __half2 a, b;
    a.x = __float2half_rn(v.x); a.y = __float2half_rn(v.y);
    b.x = __float2half_rn(v.z); b.y = __float2half_rn(v.w);
    ((__half2*)dst)[idx * 2]     = a;
    ((__half2*)dst)[idx * 2 + 1] = b;
}

// ---------------------------------------------------------------------------
// V transpose: g_vh fp16 [row][hd] -> g_vt fp16 [bh][d][j]  (verified R16)
// ---------------------------------------------------------------------------
__global__ __launch_bounds__(256) void conv_vt_kernel()
{
    __shared__ float vt[64][65];
    const int tid = threadIdx.x;
    const int bh = blockIdx.y, b = bh / HEADS, h = bh % HEADS;
    const int j0 = blockIdx.x * 64;

#pragma unroll
    for (int it = 0; it < 16; it++) {
        int idx = tid + 256 * it;
        int j = idx >> 6, d = idx & 63;
        int gj = j0 + j;
        float vvv = 0.0f;
        if (gj < NSEQ)
            vvv = __half2float(g_vh[(size_t)(b * NSEQ + gj) * CDIM + h * HD + d]);
        vt[j][d] = vvv;
    }
    __syncthreads();
#pragma unroll
    for (int it = 0; it < 16; it++) {
        int idx = tid + 256 * it;
        int d = idx >> 6, j = idx & 63;
        int gj = j0 + j;
        if (gj < NSEQ)
            g_vt[((size_t)bh * 64 + d) * NSEQP + gj] = __float2half_rn(vt[j][d]);
    }
}

// ---------------------------------------------------------------------------
// HMMA fp16 GEMM over K=768. 3-stage cp.async pipeline, ONE barrier per stage.
// which==0 (K,V proj): epilogue writes g_kc (K cols, fp16) + g_vh (V cols).
// which==1 (out proj): epilogue writes fp32 out + bias.  (verified R16)
// ---------------------------------------------------------------------------
#define GEMM_SMEM 98304   // 3 stages x (A 16KB + B 16KB)

__global__ __launch_bounds__(256, 2) void gemm_mma_kernel(
    int which, const float* __restrict__ bias, float* __restrict__ outp)
{
    extern __shared__ __align__(128) char smem[];
    const uint32_t sb = smem_u32(smem);

    const __half* __restrict__ A  = which ? g_atth : g_xh;
    const __half* __restrict__ Bw = which ? g_wprjh : g_wkvh;

    const int tid  = threadIdx.x;
    const int lane = tid & 31;
    const int w    = tid >> 5;
    const int wm   = w >> 2;
    const int wn   = w & 3;
    const int n0   = blockIdx.x * 128;
    const int m0   = blockIdx.y * 128;

    float acc[4][4][4];
#pragma unroll
    for (int mi = 0; mi < 4; mi++)
#pragma unroll
        for (int ni = 0; ni < 4; ni++)
#pragma unroll
            for (int c = 0; c < 4; c++) acc[mi][ni][c] = 0.0f;

    const int srow = tid >> 3;
    const int q    = tid & 7;

    auto issue_stage = [&](int ch, int buf) {
        const uint32_t sa_base = sb + (uint32_t)buf * 32768u;
        const uint32_t sb_base = sa_base + 16384u;
#pragma unroll
        for (int u = 0; u < 4; u++) {
            const int row = srow + 32 * u;
            int am = m0 + row; if (am > MROWS - 1) am = MROWS - 1;
            const uint32_t so = SMEM_SWIZZLE_128B((uint32_t)(row * 128 + q * 16));
            CP_ASYNC16(sa_base + so, A  + (size_t)am * KH + ch * 64 + q * 8);
            CP_ASYNC16(sb_base + so, Bw + (size_t)(n0 + row) * KH + ch * 64 + q * 8);
        }
        CP_COMMIT();
    };

    const int NSTAGE = KH / 64;      // 12
    issue_stage(0, 0);
    issue_stage(1, 1);

    for (int ch = 0; ch < NSTAGE; ch++) {
        if (ch + 1 < NSTAGE) CP_WAIT1(); else CP_WAIT0();
        __syncthreads();   // stage ch resident for all; all warps done with ch-1
        if (ch + 2 < NSTAGE) issue_stage(ch + 2, (ch + 2) % 3);

        const uint32_t abase = sb + (uint32_t)(ch % 3) * 32768u;
        const uint32_t bbase = abase + 16384u;
        const int rsel = lane & 15;
        const int chi  = lane >> 4;

#pragma unroll
        for (int kk = 0; kk < 4; kk++) {
            const int c8 = kk * 2 + chi;
            uint32_t af[4][4], bfr[2][4];
#pragma unroll
            for (int mi = 0; mi < 4; mi++) {
                const int row = wm * 64 + mi * 16 + rsel;
                ldsm_x4(af[mi], abase + SMEM_SWIZZLE_128B((uint32_t)(row * 128 + c8 * 16)));
            }
#pragma unroll
            for (int g = 0; g < 2; g++) {
                const int row = wn * 32 + g * 16 + rsel;
                ldsm_x4(bfr[g], bbase + SMEM_SWIZZLE_128B((uint32_t)(row * 128 + c8 * 16)));
            }
#pragma unroll
            for (int mi = 0; mi < 4; mi++)
#pragma unroll
                for (int ni = 0; ni < 4; ni++) {
                    const int g = ni >> 1, o = ni & 1;
                    mma_16816(acc[mi][ni], af[mi], bfr[g][o], bfr[g][o + 2]);
                }
        }
        // no trailing barrier: next-iter top barrier orders buffer reuse
    }

    // Epilogue
#pragma unroll
    for (int mi = 0; mi < 4; mi++) {
        const int r0 = m0 + wm * 64 + mi * 16 + (lane >> 2);
        const int r1 = r0 + 8;
#pragma unroll
        for (int ni = 0; ni < 4; ni++) {
            const int col = n0 + wn * 32 + ni * 8 + (lane & 3) * 2;
            const float b0v = bias[col], b1v = bias[col + 1];
            if (which) {
                if (r0 < MROWS) {
                    float2 v = make_float2(acc[mi][ni][0] + b0v, acc[mi][ni][1] + b1v);
                    *(float2*)(outp + (size_t)r0 * CDIM + col) = v;
                }
                if (r1 < MROWS) {
                    float2 v = make_float2(acc[mi][ni][2] + b0v, acc[mi][ni][3] + b1v);
                    *(float2*)(outp + (size_t)r1 * CDIM + col) = v;
                }
            } else {
                // K,V projection: K cols -> g_kc fp16; V cols -> g_vh fp16.
#pragma unroll
                for (int half2sel = 0; half2sel < 2; half2sel++) {
                    const int r = half2sel ? r1 : r0;
                    if (r >= MROWS) continue;
                    const float v0 = acc[mi][ni][half2sel * 2]     + b0v;
                    const float v1 = acc[mi][ni][half2sel * 2 + 1] + b1v;
                    __half2 hv;
                    hv.x = __float2half_rn(v0); hv.y = __float2half_rn(v1);
                    if (col < CDIM) {
                        const int bb = r / NSEQ, j = r - bb * NSEQ;
                        const int hh = col >> 6, d = col & 63;
                        *(__half2*)(g_kc + ((size_t)(bb * HEADS + hh) * NSEQP + j) * 64 + d) = hv;
                    } else {
                        *(__half2*)(g_vh + (size_t)r * CDIM + (col - CDIM)) = hv;
                    }
                }
            }
        }
    }
}

// ---------------------------------------------------------------------------
// Tensor-core flash attention — EXACT R15 structure (best measured attn):
// single-buffered j-tiles, smem 48.5KB, (256,2), direct fp16 epilogue.
// ---------------------------------------------------------------------------
#define AK_KI   0
#define AK_KJ   16384
#define AK_VT   24576
#define AK_P    32768
#define AK_FTAB 49152
#define AK_SMEM (49152 + 256)

__global__ __launch_bounds__(256, 2) void attn_mma_kernel()
{
    extern __shared__ __align__(128) char sm[];
    const uint32_t sb = smem_u32(sm);
    float* ftab = (float*)(sm + AK_FTAB);

    const int tid = threadIdx.x, lane = tid & 31, w = tid >> 5;
    const int bh = blockIdx.y, b = bh / HEADS, h = bh % HEADS;
    const int i0 = blockIdx.x * 128;

    if (tid < 63) { float xx = (float)tid - 31.0f; ftab[tid] = __expf(-xx * xx * 0.02f); }

    // Ki tile [128][64] fp16, loaded once
    {
        const int srow = tid >> 3, q = tid & 7;
#pragma unroll
        for (int u = 0; u < 4; u++) {
            int row = srow + 32 * u;
            int gi = i0 + row; if (gi > NSEQ - 1) gi = NSEQ - 1;
            const __half* src = g_kc + ((size_t)bh * NSEQP + gi) * 64 + q * 8;
            uint32_t so = SMEM_SWIZZLE_128B((uint32_t)(row * 128 + q * 16));
            CP_ASYNC16(sb + AK_KI + so, src);
        }
        CP_COMMIT();
    }

    const int rsel = lane & 15, chi = lane >> 4;
    const int rA = w * 16 + (lane >> 2);
    const int iA = i0 + rA, iB = iA + 8;
    const bool okA = (iA >= 8) && (iA < NSEQ);
    const bool okB = (iB >= 8) && (iB < NSEQ);
    const int qiA1 = (iA - 8) >> 5, qiA2 = (iA - 8) & 31;
    const int qiB1 = (iB - 8) >> 5, qiB2 = (iB - 8) & 31;

    float mA = -1e30f, mB = -1e30f, lA = 0.0f, lB = 0.0f;
    float O[8][4];
#pragma unroll
    for (int ni = 0; ni < 8; ni++)
#pragma unroll
        for (int c = 0; c < 4; c++) O[ni][c] = 0.0f;

    const float scale = 0.125f;

    for (int jt = 0; jt < NSEQP; jt += 64) {
        __syncthreads();   // prior tile fully consumed by all warps
        {
            const int srow = tid >> 3, q = tid & 7;
#pragma unroll
            for (int u = 0; u < 2; u++) {
                int row = srow + 32 * u;
                const __half* sk = g_kc + ((size_t)bh * NSEQP + jt + row) * 64 + q * 8;
                const __half* sv = g_vt + ((size_t)bh * 64 + row) * NSEQP + jt + q * 8;
                uint32_t so = SMEM_SWIZZLE_128B((uint32_t)(row * 128 + q * 16));
                CP_ASYNC16(sb + AK_KJ + so, sk);
                CP_ASYNC16(sb + AK_VT + so, sv);
            }
            CP_COMMIT(); CP_WAIT0();
        }
        __syncthreads();

        // ---- S = Ki.Kj^T (single fp16 pass) ----
        float s[8][4];
#pragma unroll
        for (int ni = 0; ni < 8; ni++)
#pragma unroll
            for (int c = 0; c < 4; c++) s[ni][c] = 0.0f;

#pragma unroll
        for (int kk = 0; kk < 4; kk++) {
            const int c8 = kk * 2 + chi;
            uint32_t af[4], bfr[4][4];
            ldsm_x4(af, sb + AK_KI +
                    SMEM_SWIZZLE_128B((uint32_t)((w * 16 + rsel) * 128 + c8 * 16)));
#pragma unroll
            for (int g = 0; g < 4; g++)
                ldsm_x4(bfr[g], sb + AK_KJ +
                        SMEM_SWIZZLE_128B((uint32_t)((g * 16 + rsel) * 128 + c8 * 16)));
#pragma unroll
            for (int ni = 0; ni < 8; ni++)
                mma_16816(s[ni], af, bfr[ni >> 1][ni & 1], bfr[ni >> 1][(ni & 1) + 2]);
        }

        // ---- scale + gaussian bias + tail mask ----
#pragma unroll
        for (int ni = 0; ni < 8; ni++) {
            const int jbase = jt + ni * 8 + ((lane & 3) << 1);
#pragma unroll
            for (int c = 0; c < 4; c++) {
                const int j = jbase + (c & 1);
                float val = s[ni][c] * scale;
                const bool ok = (c < 2) ? okA : okB;
                const int q1 = (c < 2) ? qiA1 : qiB1;
                const int q2 = (c < 2) ? qiA2 : qiB2;
                if (j < NSEQ) {
                    if (ok && j >= 8)
                        val += ftab[q1 - ((j - 8) >> 5) + 31] * ftab[q2 - ((j - 8) & 31) + 31];
                } else val = -1e30f;
                s[ni][c] = val;
            }
        }

        // ---- online softmax ----
        float tA = -1e30f, tB = -1e30f;
#pragma unroll
        for (int ni = 0; ni < 8; ni++) {
            tA = fmaxf(tA, fmaxf(s[ni][0], s[ni][1]));
            tB = fmaxf(tB, fmaxf(s[ni][2], s[ni][3]));
        }
        tA = fmaxf(tA, __shfl_xor_sync(0xffffffffu, tA, 1));
        tA = fmaxf(tA, __shfl_xor_sync(0xffffffffu, tA, 2));
        tB = fmaxf(tB, __shfl_xor_sync(0xffffffffu, tB, 1));
        tB = fmaxf(tB, __shfl_xor_sync(0xffffffffu, tB, 2));
        const float mnA = fmaxf(mA, tA), mnB = fmaxf(mB, tB);
        const float cA = __expf(mA - mnA), cB = __expf(mB - mnB);
        float rsA = 0.0f, rsB = 0.0f;
#pragma unroll
        for (int ni = 0; ni < 8; ni++) {
            s[ni][0] = __expf(s[ni][0] - mnA); rsA += s[ni][0];
            s[ni][1] = __expf(s[ni][1] - mnA); rsA += s[ni][1];
            s[ni][2] = __expf(s[ni][2] - mnB); rsB += s[ni][2];
            s[ni][3] = __expf(s[ni][3] - mnB); rsB += s[ni][3];
        }
        rsA += __shfl_xor_sync(0xffffffffu, rsA, 1);
        rsA += __shfl_xor_sync(0xffffffffu, rsA, 2);
        rsB += __shfl_xor_sync(0xffffffffu, rsB, 1);
        rsB += __shfl_xor_sync(0xffffffffu, rsB, 2);
        lA = lA * cA + rsA; lB = lB * cB + rsB;
        mA = mnA; mB = mnB;

        // ---- P -> smem (fp16, warp-private rows) + O rescale ----
        const uint32_t rowoffA = (uint32_t)((w * 16 + (lane >> 2)) * 128 + (lane & 3) * 4);
        const uint32_t rowoffB = rowoffA + 8 * 128;
#pragma unroll
        for (int ni = 0; ni < 8; ni++) {
            O[ni][0] *= cA; O[ni][1] *= cA; O[ni][2] *= cB; O[ni][3] *= cB;

            __half2 pv;
            pv.x = __float2half_rn(s[ni][0]); pv.y = __float2half_rn(s[ni][1]);
            *(__half2*)(sm + AK_P + SMEM_SWIZZLE_128B(rowoffA + ni * 16)) = pv;

            __half2 pv2;
            pv2.x = __float2half_rn(s[ni][2]); pv2.y = __float2half_rn(s[ni][3]);
            *(__half2*)(sm + AK_P + SMEM_SWIZZLE_128B(rowoffB + ni * 16)) = pv2;
        }
        __syncwarp();

        // ---- O += P.V (single fp16 pass) ----
#pragma unroll
        for (int kk = 0; kk < 4; kk++) {
            const int c8 = kk * 2 + chi;
            uint32_t af[4], bfr[4][4];
            ldsm_x4(af, sb + AK_P +
                    SMEM_SWIZZLE_128B((uint32_t)((w * 16 + rsel) * 128 + c8 * 16)));
#pragma unroll
            for (int g = 0; g < 4; g++)
                ldsm_x4(bfr[g], sb + AK_VT +
                        SMEM_SWIZZLE_128B((uint32_t)((g * 16 + rsel) * 128 + c8 * 16)));
#pragma unroll
            for (int ni = 0; ni < 8; ni++)
                mma_16816(O[ni], af, bfr[ni >> 1][ni & 1], bfr[ni >> 1][(ni & 1) + 2]);
        }
    }

    // ---- epilogue: normalize, write g_atth fp16 directly (coalesced half2) ----
    const float invA = 1.0f / lA, invB = 1.0f / lB;
#pragma unroll
    for (int ni = 0; ni < 8; ni++) {
        const int d = ni * 8 + ((lane & 3) << 1);
        if (iA < NSEQ) {
            __half2 v;
            v.x = __float2half_rn(O[ni][0] * invA);
            v.y = __float2half_rn(O[ni][1] * invA);
            *(__half2*)(g_atth + (size_t)(b * NSEQ + iA) * KH + h * HD + d) = v;
        }
        if (iB < NSEQ) {
            __half2 v;
            v.x = __float2half_rn(O[ni][2] * invB);
            v.y = __float2half_rn(O[ni][3] * invB);
            *(__half2*)(g_atth + (size_t)(b * NSEQ + iB) * KH + h * HD + d) = v;
        }
    }
}

// ---------------------------------------------------------------------------
extern "C" void kernel_launch(void* const* d_in, const int* in_sizes, int n_in,
                              void* d_out, int out_size)
{
    const float* x = nullptr;
    const float* qkv_w = nullptr;
    const float* qkv_b = nullptr;
    const float* proj_w = nullptr;
    const float* proj_b = nullptr;
    for (int i = 0; i < n_in; i++) {
        switch (in_sizes[i]) {
            case 6340608: x      = (const float*)d_in[i]; break;
            case 1769472: qkv_w  = (const float*)d_in[i]; break;
            case 2304:    qkv_b  = (const float*)d_in[i]; break;
            case 589824:  proj_w = (const float*)d_in[i]; break;
            case 768:     proj_b = (const float*)d_in[i]; break;
        }
    }
    float* out = (float*)d_out;

    cudaFuncSetAttribute(gemm_mma_kernel, cudaFuncAttributeMaxDynamicSharedMemorySize, GEMM_SMEM);
    cudaFuncSetAttribute(attn_mma_kernel, cudaFuncAttributeMaxDynamicSharedMemorySize, AK_SMEM);

    // 0) combined conversion: x, W_kv, W_proj -> fp16 (one launch)
    {
        size_t total = CV_NX + CV_NW + CV_NP;
        conv_all_kernel<<<(unsigned)((total + 255) / 256), 256>>>(x, qkv_w, proj_w);
    }
    // 1) K,V projection via fp16 HMMA -> g_kc (K, fp16 direct) + g_vh (V fp16)
    {
        dim3 grid(KVW / 128, (MROWS + 127) / 128);   // 12 x 65
        gemm_mma_kernel<<<grid, 256, GEMM_SMEM>>>(0, qkv_b + CDIM, nullptr);
    }
    // 2) V transpose -> g_vt
    {
        dim3 grid(17, NPANEL);                       // 17 x 96
        conv_vt_kernel<<<grid, 256>>>();
    }
    // 3) tensor-core flash attention -> g_atth (fp16, direct)
    {
        dim3 grid((NSEQ + 127) / 128, NPANEL);       // 9 x 96
        attn_mma_kernel<<<grid, 256, AK_SMEM>>>();
    }
    // 4) output projection via fp16 HMMA -> d_out
    {
        dim3 grid(CDIM / 128, (MROWS + 127) / 128);  // 6 x 65
        gemm_mma_kernel<<<grid, 256, GEMM_SMEM>>>(1, proj_b, out);
    }
}